// round 2
// baseline (speedup 1.0000x reference)
#include <cuda_runtime.h>
#include <cstdint>

#define NN 512
#define DD 256
#define MARGIN 0.2f

// Scratch (device globals, no allocation)
__device__ float g_mat[NN * NN];
__device__ float g_sq[NN];

// ---------------------------------------------------------------------------
// Kernel 1: squared row norms: sum_k fp32(e*e) accumulated exactly in double
// (correctly-rounded sum of the rounded fp32 products), stored as fp32.
// One block per row, 256 threads == D.
// ---------------------------------------------------------------------------
__global__ void sq_kernel(const float* __restrict__ emb) {
    __shared__ double red[256];
    int row = blockIdx.x;
    int k = threadIdx.x;
    float v = emb[row * DD + k];
    red[k] = (double)__fmul_rn(v, v);
    __syncthreads();
    #pragma unroll
    for (int off = 128; off > 0; off >>= 1) {
        if (k < off) red[k] += red[k + off];
        __syncthreads();
    }
    if (k == 0) g_sq[row] = (float)red[0];
}

// ---------------------------------------------------------------------------
// Kernel 2: Gram matrix -> squared euclidean distance matrix.
// fp64 accumulate (exact), then fp32 final combine in the reference's exact
// elementwise op order: max((sq_a + sq_n) - 2*G, 0), no FMA fusion.
// Symmetry: 136 upper-triangular 32x32 tiles; each block writes (m,n)+(n,m).
// ---------------------------------------------------------------------------
#define TS 32
__global__ void mat_kernel(const float* __restrict__ emb) {
    __shared__ double As[16][TS + 1];
    __shared__ double Bs[16][TS + 1];

    // decode triangular block index z -> (bi <= bj)
    int z = blockIdx.x;
    int bj = (int)((sqrtf(8.0f * (float)z + 1.0f) - 1.0f) * 0.5f);
    while ((bj + 1) * (bj + 2) / 2 <= z) bj++;
    while (bj * (bj + 1) / 2 > z) bj--;
    int bi = z - bj * (bj + 1) / 2;

    int m0 = bi * TS, n0 = bj * TS;
    int tid = threadIdx.x;
    int tx = tid & 15, ty = tid >> 4;

    double acc00 = 0.0, acc01 = 0.0, acc10 = 0.0, acc11 = 0.0;

    for (int k0 = 0; k0 < DD; k0 += 16) {
        #pragma unroll
        for (int q = 0; q < 2; q++) {
            int idx = tid + q * 256;      // 0..511 over 32 rows x 16 k
            int r = idx >> 4, kk = idx & 15;
            As[kk][r] = (double)emb[(m0 + r) * DD + k0 + kk];
            Bs[kk][r] = (double)emb[(n0 + r) * DD + k0 + kk];
        }
        __syncthreads();
        #pragma unroll
        for (int kk = 0; kk < 16; kk++) {
            double a0 = As[kk][ty];
            double a1 = As[kk][ty + 16];
            double b0 = Bs[kk][tx];
            double b1 = Bs[kk][tx + 16];
            acc00 = fma(a0, b0, acc00);
            acc01 = fma(a0, b1, acc01);
            acc10 = fma(a1, b0, acc10);
            acc11 = fma(a1, b1, acc11);
        }
        __syncthreads();
    }

    double accs[2][2] = {{acc00, acc01}, {acc10, acc11}};
    #pragma unroll
    for (int i = 0; i < 2; i++) {
        int m = m0 + ty + 16 * i;
        float sm = g_sq[m];
        #pragma unroll
        for (int j = 0; j < 2; j++) {
            int n = n0 + tx + 16 * j;
            float d = (float)accs[i][j];
            // ref order: (sq[a] + sq[n]) - 2*dot, then clamp — no FMA fusion
            float v = fmaxf(__fsub_rn(__fadd_rn(sm, g_sq[n]),
                                      __fmul_rn(2.0f, d)), 0.0f);
            g_mat[m * NN + n] = v;
            g_mat[n * NN + m] = v;
        }
    }
}

// ---------------------------------------------------------------------------
// Kernel 3: mask -> FLOAT32 output (bool canonicalized to f32 by harness).
// One block per anchor a (512 blocks, 256 thr).
//   s_key[n] = diffs[a,n] ? mat[a,n] : +INF   (INF - t > margin => false)
//   s_thr[p] = (sames[a,p] && p!=a) ? mat[a,p] : -1.0f  (sentinel; mat >= 0,
//              and even without the branch f-(-1) <= 0.2 is false for f>=0)
// Each warp sweeps p (stride 8); per row, lane l writes 4 coalesced float4
// (step q covers a contiguous 512B segment). Invalid rows (97%): zero stores
// only. Labels: auto-detect int32 vs int64 word layout.
// ---------------------------------------------------------------------------
__global__ void maskf_kernel(const int* __restrict__ lw, float4* __restrict__ out) {
    __shared__ __align__(16) float s_key[NN];
    __shared__ float s_thr[NN];
    __shared__ int s_not64;

    int a = blockIdx.x;
    int tid = threadIdx.x;

    if (tid == 0) s_not64 = 0;
    __syncthreads();
    // Probe words [1,3,...,511]: within 2KB, valid for both layouts.
    if (lw[2 * tid + 1] != 0) s_not64 = 1;
    __syncthreads();
    bool is64 = (s_not64 == 0);

    const float INF = __int_as_float(0x7f800000);
    int la = is64 ? lw[2 * a] : lw[a];
    for (int n = tid; n < NN; n += 256) {
        int ln = is64 ? lw[2 * n] : lw[n];
        float m = g_mat[a * NN + n];
        bool same = (ln == la);
        s_key[n] = same ? INF : m;                    // diffs gate
        s_thr[n] = (same && n != a) ? m : -1.0f;      // sames gate (sentinel)
    }
    __syncthreads();

    int warp = tid >> 5, lane = tid & 31;
    const float4* k4 = (const float4*)s_key;

    for (int p = warp; p < NN; p += 8) {
        float t = s_thr[p];
        float4* orow = out + ((size_t)a * NN + p) * (NN / 4);
        if (t < 0.0f) {
            float4 z = make_float4(0.0f, 0.0f, 0.0f, 0.0f);
            #pragma unroll
            for (int q = 0; q < 4; q++)
                orow[q * 32 + lane] = z;
        } else {
            #pragma unroll
            for (int q = 0; q < 4; q++) {
                float4 f = k4[q * 32 + lane];
                float4 r;
                // ref: (mat[a,n] - mat[a,p]) <= MARGIN, fp32, no fusion.
                r.x = (__fsub_rn(f.x, t) <= MARGIN) ? 1.0f : 0.0f;
                r.y = (__fsub_rn(f.y, t) <= MARGIN) ? 1.0f : 0.0f;
                r.z = (__fsub_rn(f.z, t) <= MARGIN) ? 1.0f : 0.0f;
                r.w = (__fsub_rn(f.w, t) <= MARGIN) ? 1.0f : 0.0f;
                orow[q * 32 + lane] = r;
            }
        }
    }
}

// ---------------------------------------------------------------------------
extern "C" void kernel_launch(void* const* d_in, const int* in_sizes, int n_in,
                              void* d_out, int out_size) {
    const float* emb = (const float*)d_in[0];
    const int* labels = (const int*)d_in[1];
    (void)in_sizes; (void)n_in; (void)out_size;

    sq_kernel<<<NN, 256>>>(emb);
    mat_kernel<<<136, 256>>>(emb);
    maskf_kernel<<<NN, 256>>>(labels, (float4*)d_out);
}

// round 3
// speedup vs baseline: 1.7095x; 1.7095x over previous
#include <cuda_runtime.h>
#include <cstdint>

#define NN 512
#define DD 256
#define MARGIN 0.2f

// Scratch (device global, no allocation)
__device__ float g_mat[NN * NN];

// ---------------------------------------------------------------------------
// Packed f32x2 helpers (Blackwell). Subtraction/negation built from exact
// fma/mul by -1 (multiplying by -1 is exact, so TwoSum algebra is preserved).
// ---------------------------------------------------------------------------
__device__ __forceinline__ uint64_t pk2(float lo, float hi) {
    uint64_t d; asm("mov.b64 %0, {%1,%2};" : "=l"(d) : "f"(lo), "f"(hi)); return d;
}
__device__ __forceinline__ void upk2(uint64_t v, float& lo, float& hi) {
    asm("mov.b64 {%0,%1}, %2;" : "=f"(lo), "=f"(hi) : "l"(v));
}
__device__ __forceinline__ uint64_t mul2(uint64_t a, uint64_t b) {
    uint64_t d; asm("mul.rn.f32x2 %0, %1, %2;" : "=l"(d) : "l"(a), "l"(b)); return d;
}
__device__ __forceinline__ uint64_t add2(uint64_t a, uint64_t b) {
    uint64_t d; asm("add.rn.f32x2 %0, %1, %2;" : "=l"(d) : "l"(a), "l"(b)); return d;
}
__device__ __forceinline__ uint64_t fma2(uint64_t a, uint64_t b, uint64_t c) {
    uint64_t d; asm("fma.rn.f32x2 %0, %1, %2, %3;" : "=l"(d) : "l"(a), "l"(b), "l"(c)); return d;
}
#define NEG1_2 0xBF800000BF800000ULL
__device__ __forceinline__ uint64_t neg2(uint64_t x) { return mul2(x, NEG1_2); }
__device__ __forceinline__ uint64_t sub2(uint64_t a, uint64_t b) { return fma2(b, NEG1_2, a); }

// Compensated accumulate of product a*b into (S, C): Dot2 (Ogita-Rump-Oishi).
__device__ __forceinline__ void dot2_step(uint64_t a, uint64_t b,
                                          uint64_t& S, uint64_t& C) {
    uint64_t p  = mul2(a, b);
    uint64_t e  = fma2(a, b, neg2(p));   // exact product error
    uint64_t t  = add2(S, p);            // TwoSum(S, p)
    uint64_t bp = sub2(t, S);
    uint64_t d1 = sub2(S, sub2(t, bp));
    uint64_t d2 = sub2(p, bp);
    C = add2(C, add2(e, add2(d1, d2)));
    S = t;
}

// Scalar compensated helpers for row norms
__device__ __forceinline__ void sq_step(float v, float& s, float& c) {
    float p = __fmul_rn(v, v);
    float e = __fmaf_rn(v, v, -p);
    float t = __fadd_rn(s, p);
    float bp = __fsub_rn(t, s);
    float err = __fadd_rn(__fsub_rn(s, __fsub_rn(t, bp)), __fsub_rn(p, bp));
    c = __fadd_rn(c, __fadd_rn(err, e));
    s = t;
}
__device__ __forceinline__ void cs_merge(float& s, float& c, float s2, float c2) {
    float t = __fadd_rn(s, s2);
    float bp = __fsub_rn(t, s);
    float err = __fadd_rn(__fsub_rn(s, __fsub_rn(t, bp)), __fsub_rn(s2, bp));
    c = __fadd_rn(__fadd_rn(c, c2), err);
    s = t;
}

// ---------------------------------------------------------------------------
// Fused kernel: row norms + exact-accuracy fp32 Gram -> distance matrix.
// 136 upper-triangular 32x32 tiles; each block writes (m,n) and (n,m).
// 256 threads = 16x16; each thread owns a 2x2 output tile, with the two
// n-columns packed into one f32x2 lane pair.
// ---------------------------------------------------------------------------
__global__ void mat_kernel(const float* __restrict__ emb) {
    __shared__ float As[16][33];
    __shared__ float Bs2[16][34];   // paired layout: [kk][2*tx + (0|1)] = rows tx, tx+16
    __shared__ float s_sq[64];      // [0:32)=A rows, [32:64)=B rows

    // decode triangular block index z -> (bi <= bj)
    int z = blockIdx.x;
    int bj = (int)((sqrtf(8.0f * (float)z + 1.0f) - 1.0f) * 0.5f);
    while ((bj + 1) * (bj + 2) / 2 <= z) bj++;
    while (bj * (bj + 1) / 2 > z) bj--;
    int bi = z - bj * (bj + 1) / 2;

    int m0 = bi * 32, n0 = bj * 32;
    int tid = threadIdx.x;
    int warp = tid >> 5, lane = tid & 31;
    int tx = tid & 15, ty = tid >> 4;

    // ---- per-block row norms (identical algorithm in every block) ----
    #pragma unroll
    for (int r = 0; r < 8; r++) {
        int rl = warp * 8 + r;                       // 0..63
        int grow = (rl < 32) ? (m0 + rl) : (n0 + rl - 32);
        const float4* r4 = (const float4*)(emb + grow * DD);
        float4 x = r4[lane];
        float4 y = r4[lane + 32];
        float s = 0.0f, c = 0.0f;
        sq_step(x.x, s, c); sq_step(x.y, s, c); sq_step(x.z, s, c); sq_step(x.w, s, c);
        sq_step(y.x, s, c); sq_step(y.y, s, c); sq_step(y.z, s, c); sq_step(y.w, s, c);
        #pragma unroll
        for (int off = 16; off > 0; off >>= 1) {
            float s2 = __shfl_xor_sync(0xffffffffu, s, off);
            float c2 = __shfl_xor_sync(0xffffffffu, c, off);
            cs_merge(s, c, s2, c2);
        }
        if (lane == 0) s_sq[rl] = __fadd_rn(s, c);
    }
    __syncthreads();

    // ---- main loop: compensated fp32x2 Gram ----
    uint64_t S0 = 0, C0 = 0, S1 = 0, C1 = 0;   // 0.0f pair bit pattern is 0

    for (int k0 = 0; k0 < DD; k0 += 16) {
        #pragma unroll
        for (int q = 0; q < 2; q++) {
            int idx = tid + q * 256;
            int r = idx >> 4, kk = idx & 15;
            As[kk][r] = emb[(m0 + r) * DD + k0 + kk];
            Bs2[kk][((r & 15) << 1) | (r >> 4)] = emb[(n0 + r) * DD + k0 + kk];
        }
        __syncthreads();
        #pragma unroll
        for (int kk = 0; kk < 16; kk++) {
            uint64_t b2 = *(const uint64_t*)&Bs2[kk][2 * tx];   // rows (tx, tx+16)
            float a0 = As[kk][ty];
            float a1 = As[kk][ty + 16];
            dot2_step(pk2(a0, a0), b2, S0, C0);
            dot2_step(pk2(a1, a1), b2, S1, C1);
        }
        __syncthreads();
    }

    float d00, d01, d10, d11;
    upk2(add2(S0, C0), d00, d01);
    upk2(add2(S1, C1), d10, d11);

    float dots[2][2] = {{d00, d01}, {d10, d11}};
    #pragma unroll
    for (int i = 0; i < 2; i++) {
        int ml = ty + 16 * i;
        int m = m0 + ml;
        float sm = s_sq[ml];
        #pragma unroll
        for (int j = 0; j < 2; j++) {
            int nl = tx + 16 * j;
            int n = n0 + nl;
            // ref order: (sq[a] + sq[n]) - 2*dot, then clamp — no FMA fusion
            float v = fmaxf(__fsub_rn(__fadd_rn(sm, s_sq[32 + nl]),
                                      __fmul_rn(2.0f, dots[i][j])), 0.0f);
            g_mat[m * NN + n] = v;
            g_mat[n * NN + m] = v;
        }
    }
}

// ---------------------------------------------------------------------------
// Mask -> FLOAT32 output. grid = (512 anchors, 4 p-chunks), 256 threads.
//   s_key[n] = diffs[a,n] ? mat[a,n] : +INF
//   s_thr[p] = (sames[a,p] && p!=a) ? mat[a,p] : -1.0f  (sentinel, mat >= 0)
// Each warp sweeps 16 p rows in its chunk; lane writes 4 coalesced float4
// per row via streaming stores. Invalid rows (97%): zero stores only.
// ---------------------------------------------------------------------------
__global__ void maskf_kernel(const int* __restrict__ lw, float4* __restrict__ out) {
    __shared__ __align__(16) float s_key[NN];
    __shared__ float s_thr[NN];
    __shared__ int s_not64;

    int a = blockIdx.x;
    int tid = threadIdx.x;

    if (tid == 0) s_not64 = 0;
    __syncthreads();
    // Probe words [1,3,...,511]: within 2KB, valid for both layouts.
    if (lw[2 * tid + 1] != 0) s_not64 = 1;
    __syncthreads();
    bool is64 = (s_not64 == 0);

    const float INF = __int_as_float(0x7f800000);
    int la = is64 ? lw[2 * a] : lw[a];
    for (int n = tid; n < NN; n += 256) {
        int ln = is64 ? lw[2 * n] : lw[n];
        float m = g_mat[a * NN + n];
        bool same = (ln == la);
        s_key[n] = same ? INF : m;                    // diffs gate
        s_thr[n] = (same && n != a) ? m : -1.0f;      // sames gate (sentinel)
    }
    __syncthreads();

    int warp = tid >> 5, lane = tid & 31;
    const float4* k4 = (const float4*)s_key;
    int p0 = blockIdx.y * 128;

    for (int p = p0 + warp; p < p0 + 128; p += 8) {
        float t = s_thr[p];
        float4* orow = out + ((size_t)a * NN + p) * (NN / 4);
        if (t < 0.0f) {
            float4 zv = make_float4(0.0f, 0.0f, 0.0f, 0.0f);
            #pragma unroll
            for (int q = 0; q < 4; q++)
                __stcs(&orow[q * 32 + lane], zv);
        } else {
            #pragma unroll
            for (int q = 0; q < 4; q++) {
                float4 f = k4[q * 32 + lane];
                float4 r;
                // ref: (mat[a,n] - mat[a,p]) <= MARGIN, fp32, no fusion.
                r.x = (__fsub_rn(f.x, t) <= MARGIN) ? 1.0f : 0.0f;
                r.y = (__fsub_rn(f.y, t) <= MARGIN) ? 1.0f : 0.0f;
                r.z = (__fsub_rn(f.z, t) <= MARGIN) ? 1.0f : 0.0f;
                r.w = (__fsub_rn(f.w, t) <= MARGIN) ? 1.0f : 0.0f;
                __stcs(&orow[q * 32 + lane], r);
            }
        }
    }
}

// ---------------------------------------------------------------------------
extern "C" void kernel_launch(void* const* d_in, const int* in_sizes, int n_in,
                              void* d_out, int out_size) {
    const float* emb = (const float*)d_in[0];
    const int* labels = (const int*)d_in[1];
    (void)in_sizes; (void)n_in; (void)out_size;

    mat_kernel<<<136, 256>>>(emb);
    maskf_kernel<<<dim3(512, 4), 256>>>(labels, (float4*)d_out);
}